// round 16
// baseline (speedup 1.0000x reference)
#include <cuda_runtime.h>
#include <cuda_bf16.h>
#include <cstdint>

#define TT 16          // time steps
#define BB 16          // batch
#define CC 256         // channels C (and Cc)
#define DD 512         // 2*C
#define HW 1024        // H*W

// ---------------------------------------------------------------------------
// Single fused kernel, one launch. Grid = 4096 blocks x 256 threads; block
// owns SIXTEEN consecutive channels of one (t,b) slice. Same 256-thread warp
// shape as the proven kernel, but SIXTEEN float4 loads hoisted per thread
// (MLP=16). __launch_bounds__(256,3) gives ptxas an 85-reg budget: 64
// payload regs + overhead fit WITHOUT spilling, 3 CTAs/SM -> 24 warps x
// 16 loads = 192KB in flight per SM (vs 160KB at MLP=8).
//
// Phase A: LIF scan (all 256 threads, one per cc); 16 independent cond
//          loads, register recurrence, keep spike at this block's t.
// Phase B: 32 params = 32 dot products of length 256; 8 lanes per output,
//          conflict-free smem + coalesced W, 3-stage shfl reduce.
// Phase C: 16 hoisted float4 loads; params read from smem AT USE TIME
//          (2 live regs, not 32); streaming stores.
// ---------------------------------------------------------------------------
__global__ void __launch_bounds__(256, 3) fused_kernel(
    const float4* __restrict__ x,
    const float*  __restrict__ cond,
    const float*  __restrict__ Wm,
    const float*  __restrict__ bias,
    float4*       __restrict__ out) {
    __shared__ float s_sp[CC];      // spikes at this block's t
    __shared__ float s_par[32];     // 16 gamma | 16 beta

    int tid  = threadIdx.x;
    unsigned row0 = blockIdx.x * 16;        // first channel-row of block
    unsigned tb   = row0 >> 8;              // t*BB + b
    unsigned c0   = row0 & (CC - 1);        // 16-aligned channel offset
    int t = (int)(tb >> 4);                 // this block's time step
    int b = (int)(tb & 15);

    // --- Phase A: LIF scan for (b, cc=tid); keep spike at step t ---
    {
        int cc = tid;
        float xv[TT];
#pragma unroll
        for (int tp = 0; tp < TT; ++tp)     // independent loads, MLP=16
            xv[tp] = cond[(tp * BB + b) * CC + cc];
        float v = 0.0f, s_t = 0.0f;
#pragma unroll
        for (int tp = 0; tp < TT; ++tp) {
            v = v + (xv[tp] - v) * 0.5f;             // charge (TAU=2)
            float s = (v >= 1.0f) ? 1.0f : 0.0f;     // fire
            if (tp == t) s_t = s;                    // predicated select
            v = (1.0f - s) * v;                      // hard reset
        }
        s_sp[cc] = s_t;
    }
    __syncthreads();

    // --- Phase B: 32 dot products (16 gamma rows, 16 beta rows) ---
    {
        int o  = tid >> 3;                  // output 0..31
        int ch = tid & 7;                   // k-chunk lane 0..7
        int d  = (o < 16) ? (int)(c0 + o) : (int)(CC + c0 + (o - 16));
        const float* __restrict__ wr = Wm + (size_t)d * CC;

        float a = 0.0f;
#pragma unroll
        for (int i = 0; i < 32; ++i) {
            int k = i * 8 + ch;             // conflict-free smem, coalesced W
            a = fmaf(s_sp[k], wr[k], a);
        }
#pragma unroll
        for (int m = 4; m >= 1; m >>= 1)    // reduce within 8-lane group
            a += __shfl_xor_sync(0xFFFFFFFFu, a, m);
        if (ch == 0) s_par[o] = a + bias[d];
    }
    __syncthreads();

    // --- Phase C: 16 hoisted float4 loads (MLP=16), params from smem ---
    size_t base = (size_t)row0 * 256 + tid;

    float4 v0  = x[base];
    float4 v1  = x[base + 256];
    float4 v2  = x[base + 512];
    float4 v3  = x[base + 768];
    float4 v4  = x[base + 1024];
    float4 v5  = x[base + 1280];
    float4 v6  = x[base + 1536];
    float4 v7  = x[base + 1792];
    float4 v8  = x[base + 2048];
    float4 v9  = x[base + 2304];
    float4 v10 = x[base + 2560];
    float4 v11 = x[base + 2816];
    float4 v12 = x[base + 3072];
    float4 v13 = x[base + 3328];
    float4 v14 = x[base + 3584];
    float4 v15 = x[base + 3840];

    float g, be;
    float4 o;
#define FILM_ROW(J, V, OFF)                                              \
    g  = 1.0f + s_par[J];                                                \
    be = s_par[16 + J];                                                  \
    o.x = fmaf(g, V.x, be); o.y = fmaf(g, V.y, be);                      \
    o.z = fmaf(g, V.z, be); o.w = fmaf(g, V.w, be);                      \
    __stcs(&out[base + OFF], o);

    FILM_ROW(0,  v0,  0)
    FILM_ROW(1,  v1,  256)
    FILM_ROW(2,  v2,  512)
    FILM_ROW(3,  v3,  768)
    FILM_ROW(4,  v4,  1024)
    FILM_ROW(5,  v5,  1280)
    FILM_ROW(6,  v6,  1536)
    FILM_ROW(7,  v7,  1792)
    FILM_ROW(8,  v8,  2048)
    FILM_ROW(9,  v9,  2304)
    FILM_ROW(10, v10, 2560)
    FILM_ROW(11, v11, 2816)
    FILM_ROW(12, v12, 3072)
    FILM_ROW(13, v13, 3328)
    FILM_ROW(14, v14, 3584)
    FILM_ROW(15, v15, 3840)
#undef FILM_ROW
}

// ---------------------------------------------------------------------------
extern "C" void kernel_launch(void* const* d_in, const int* in_sizes, int n_in,
                              void* d_out, int out_size) {
    const float* x    = (const float*)d_in[0];   // [T,B,C,H,W]
    const float* cond = (const float*)d_in[1];   // [T,B,Cc]
    const float* Wm   = (const float*)d_in[2];   // [2C,Cc]
    const float* bias = (const float*)d_in[3];   // [2C]
    float* out = (float*)d_out;

    fused_kernel<<<TT * BB * CC / 16, 256>>>(
        (const float4*)x, cond, Wm, bias, (float4*)out);
}

// round 17
// speedup vs baseline: 1.0259x; 1.0259x over previous
#include <cuda_runtime.h>
#include <cuda_bf16.h>
#include <cstdint>

#define TT 16          // time steps
#define BB 16          // batch
#define CC 256         // channels C (and Cc)
#define DD 512         // 2*C
#define HW 1024        // H*W

// ---------------------------------------------------------------------------
// FINAL KERNEL (best measured: 84.06us total, 79.0us kernel @ ~6.2TB/s,
// the path-independent LTS throughput ceiling on this part).
//
// Single fused kernel, one launch. Grid = 8192 blocks x 256 threads; block
// owns 8 consecutive channels of one (t,b) slice -- the proven 256-thread /
// MLP=8 shape (search over MLP {1,4,8,16}, block {256,512}, cache hints,
// and 2-kernel/persistent/PDL structures all converged here).
//
// Phase A: block-local LIF scan; thread cc loads cond[(t',b,cc)] for all 16
//          t' (independent -> MLP=16, L2-resident after first wave), runs
//          the recurrence in registers, keeps the spike at THIS block's t.
// Phase B: the 16 params this block needs = 16 dot products of length 256.
//          16 threads per output, conflict-free smem + coalesced W,
//          4-stage shfl reduce.
// Phase C: MLP=8 FiLM body (8 hoisted float4 loads), streaming ld/st.
// ---------------------------------------------------------------------------
__global__ void __launch_bounds__(256) fused_kernel(
    const float4* __restrict__ x,
    const float*  __restrict__ cond,
    const float*  __restrict__ Wm,
    const float*  __restrict__ bias,
    float4*       __restrict__ out) {
    __shared__ float s_sp[CC];      // spikes at this block's t
    __shared__ float s_par[16];     // 8 gamma | 8 beta

    int tid  = threadIdx.x;
    unsigned row0 = blockIdx.x * 8;         // first channel-row
    unsigned tb   = row0 >> 8;              // t*BB + b
    unsigned c0   = row0 & (CC - 1);
    int t = (int)(tb >> 4);                 // this block's time step
    int b = (int)(tb & 15);

    // --- Phase A: LIF scan for (b, cc=tid); keep spike at step t ---
    {
        int cc = tid;
        float xv[TT];
#pragma unroll
        for (int tp = 0; tp < TT; ++tp)     // independent loads, MLP=16
            xv[tp] = cond[(tp * BB + b) * CC + cc];
        float v = 0.0f, s_t = 0.0f;
#pragma unroll
        for (int tp = 0; tp < TT; ++tp) {
            v = v + (xv[tp] - v) * 0.5f;             // charge (TAU=2)
            float s = (v >= 1.0f) ? 1.0f : 0.0f;     // fire
            if (tp == t) s_t = s;                    // predicated select
            v = (1.0f - s) * v;                      // hard reset
        }
        s_sp[cc] = s_t;
    }
    __syncthreads();

    // --- Phase B: 16 dot products (8 gamma rows, 8 beta rows) ---
    {
        int o  = tid >> 4;                  // output 0..15
        int ch = tid & 15;                  // k-chunk lane 0..15
        int d  = (o < 8) ? (int)(c0 + o) : (int)(CC + c0 + (o - 8));
        const float* __restrict__ wr = Wm + (size_t)d * CC;

        float a = 0.0f;
#pragma unroll
        for (int i = 0; i < 16; ++i) {
            int k = i * 16 + ch;            // conflict-free smem, coalesced W
            a = fmaf(s_sp[k], wr[k], a);
        }
#pragma unroll
        for (int m = 8; m >= 1; m >>= 1)    // reduce within 16-lane group
            a += __shfl_xor_sync(0xFFFFFFFFu, a, m);
        if (ch == 0) s_par[o] = a + bias[d];
    }
    __syncthreads();

    // --- Phase C: FiLM body, streaming loads/stores ---
    size_t base = (size_t)row0 * 256 + tid;

    float4 v0 = __ldcs(&x[base]);
    float4 v1 = __ldcs(&x[base + 256]);
    float4 v2 = __ldcs(&x[base + 512]);
    float4 v3 = __ldcs(&x[base + 768]);
    float4 v4 = __ldcs(&x[base + 1024]);
    float4 v5 = __ldcs(&x[base + 1280]);
    float4 v6 = __ldcs(&x[base + 1536]);
    float4 v7 = __ldcs(&x[base + 1792]);

    float g0 = 1.0f + s_par[0], g1 = 1.0f + s_par[1];
    float g2 = 1.0f + s_par[2], g3 = 1.0f + s_par[3];
    float g4 = 1.0f + s_par[4], g5 = 1.0f + s_par[5];
    float g6 = 1.0f + s_par[6], g7 = 1.0f + s_par[7];
    float b0 = s_par[8],  b1 = s_par[9],  b2 = s_par[10], b3 = s_par[11];
    float b4 = s_par[12], b5 = s_par[13], b6 = s_par[14], b7 = s_par[15];

    float4 o;
    o.x = fmaf(g0, v0.x, b0); o.y = fmaf(g0, v0.y, b0);
    o.z = fmaf(g0, v0.z, b0); o.w = fmaf(g0, v0.w, b0);
    __stcs(&out[base], o);
    o.x = fmaf(g1, v1.x, b1); o.y = fmaf(g1, v1.y, b1);
    o.z = fmaf(g1, v1.z, b1); o.w = fmaf(g1, v1.w, b1);
    __stcs(&out[base + 256], o);
    o.x = fmaf(g2, v2.x, b2); o.y = fmaf(g2, v2.y, b2);
    o.z = fmaf(g2, v2.z, b2); o.w = fmaf(g2, v2.w, b2);
    __stcs(&out[base + 512], o);
    o.x = fmaf(g3, v3.x, b3); o.y = fmaf(g3, v3.y, b3);
    o.z = fmaf(g3, v3.z, b3); o.w = fmaf(g3, v3.w, b3);
    __stcs(&out[base + 768], o);
    o.x = fmaf(g4, v4.x, b4); o.y = fmaf(g4, v4.y, b4);
    o.z = fmaf(g4, v4.z, b4); o.w = fmaf(g4, v4.w, b4);
    __stcs(&out[base + 1024], o);
    o.x = fmaf(g5, v5.x, b5); o.y = fmaf(g5, v5.y, b5);
    o.z = fmaf(g5, v5.z, b5); o.w = fmaf(g5, v5.w, b5);
    __stcs(&out[base + 1280], o);
    o.x = fmaf(g6, v6.x, b6); o.y = fmaf(g6, v6.y, b6);
    o.z = fmaf(g6, v6.z, b6); o.w = fmaf(g6, v6.w, b6);
    __stcs(&out[base + 1536], o);
    o.x = fmaf(g7, v7.x, b7); o.y = fmaf(g7, v7.y, b7);
    o.z = fmaf(g7, v7.z, b7); o.w = fmaf(g7, v7.w, b7);
    __stcs(&out[base + 1792], o);
}

// ---------------------------------------------------------------------------
extern "C" void kernel_launch(void* const* d_in, const int* in_sizes, int n_in,
                              void* d_out, int out_size) {
    const float* x    = (const float*)d_in[0];   // [T,B,C,H,W]
    const float* cond = (const float*)d_in[1];   // [T,B,Cc]
    const float* Wm   = (const float*)d_in[2];   // [2C,Cc]
    const float* bias = (const float*)d_in[3];   // [2C]
    float* out = (float*)d_out;

    fused_kernel<<<TT * BB * CC / 8, 256>>>(
        (const float4*)x, cond, Wm, bias, (float4*)out);
}